// round 8
// baseline (speedup 1.0000x reference)
#include <cuda_runtime.h>
#include <cuda_bf16.h>
#include <cstdint>

// LJ constants (match reference); sigma=1, cutoff=5
#define EPSILON 1.0f
#define SHIFT_F (4.0f * (1.0f/244140625.0f - 1.0f/15625.0f))

// Replicated accumulation scratch, fully L2-resident (3.2 MB static).
// NREP=8 kills per-address atomic contention (measured ladder: NREP=1
// edge≈85us, NREP>=8 edge≈70us flat).
//
// ZERO INVARIANT: __device__ globals are zero-initialized at module load.
// lj_reduce_clear reads each scratch word exactly once and writes 0 back,
// so scratch is zero again at the end of every kernel_launch call —
// inductively zero at entry to every call (correctness run, every graph
// replay). No separate zeroing kernel needed.
#define NREP 8
#define MAX_ATOMS 100000
#define REP_STRIDE (MAX_ATOMS + 128)   // divisible by 4
__device__ __align__(16) float g_scratch[NREP * REP_STRIDE];

__device__ __forceinline__ float lj_half_e(float x, float y, float z) {
    float r2   = fmaf(x, x, fmaf(y, y, z * z));
    float inv2 = 1.0f / r2;
    float sr6  = inv2 * inv2 * inv2;
    float e    = 4.0f * EPSILON * fmaf(sr6, sr6, -sr6) - SHIFT_F;
    return 0.5f * e;
}

// Scalar 1-edge/thread (proven best; kernel is REDG-lane-bound).
__global__ void __launch_bounds__(256)
lj_edge_kernel_rep(const float* __restrict__ dist,
                   const int* __restrict__ atom_a,
                   const int* __restrict__ atom_b,
                   int n_edges) {
    int i = blockIdx.x * blockDim.x + threadIdx.x;
    if (i >= n_edges) return;

    float x = dist[3 * i + 0];
    float y = dist[3 * i + 1];
    float z = dist[3 * i + 2];
    float h = lj_half_e(x, y, z);

    int ia = atom_a[i];
    int ib = atom_b[i];

    float* rep = g_scratch + (i & (NREP - 1)) * REP_STRIDE;
    atomicAdd(rep + ia, h);   // RED.ADD, fire-and-forget
    atomicAdd(rep + ib, h);
}

// Reduce NREP replicas -> out AND clear scratch back to zero.
// 4 atoms/thread via float4. Also clears the padding tail so the whole
// array returns to zero (atoms only ever land in [0, n_atoms), but keep
// the invariant exact for the full REP_STRIDE span we might touch).
__global__ void __launch_bounds__(256)
lj_reduce_clear_v4(float* __restrict__ out, int n_atoms) {
    int t = blockIdx.x * blockDim.x + threadIdx.x;
    int base = 4 * t;
    if (base >= n_atoms) return;

    const float4 zero4 = make_float4(0.f, 0.f, 0.f, 0.f);
    float4 s = zero4;
    #pragma unroll
    for (int r = 0; r < NREP; r++) {
        float4* p = reinterpret_cast<float4*>(g_scratch + r * REP_STRIDE + base);
        const float4 v = *p;
        s.x += v.x; s.y += v.y; s.z += v.z; s.w += v.w;
        *p = zero4;   // restore zero invariant for next launch
    }
    if (base + 3 < n_atoms) {
        *reinterpret_cast<float4*>(out + base) = s;
    } else {
        float sv[4] = {s.x, s.y, s.z, s.w};
        for (int k = 0; k < 4 && base + k < n_atoms; k++) out[base + k] = sv[k];
    }
}

// Fallback (atom count exceeds static scratch): direct atomics.
__global__ void lj_zero_out(float* __restrict__ out, int n) {
    int i = blockIdx.x * blockDim.x + threadIdx.x;
    if (i < n) out[i] = 0.0f;
}
__global__ void lj_edge_kernel_direct(const float* __restrict__ dist,
                                      const int* __restrict__ atom_a,
                                      const int* __restrict__ atom_b,
                                      float* __restrict__ out,
                                      int n_edges) {
    int i = blockIdx.x * blockDim.x + threadIdx.x;
    if (i >= n_edges) return;
    float h = lj_half_e(dist[3*i], dist[3*i+1], dist[3*i+2]);
    atomicAdd(out + atom_a[i], h);
    atomicAdd(out + atom_b[i], h);
}

extern "C" void kernel_launch(void* const* d_in, const int* in_sizes, int n_in,
                              void* d_out, int out_size) {
    const float* dist   = (const float*)d_in[0];
    const int*   atom_a = (const int*)d_in[1];   // JAX x64-disabled: int32
    const int*   atom_b = (const int*)d_in[2];
    float* out = (float*)d_out;

    int n_edges = in_sizes[1];
    int n_atoms = out_size;
    const int T = 256;

    if (n_atoms <= MAX_ATOMS) {
        lj_edge_kernel_rep<<<(n_edges + T - 1) / T, T>>>(dist, atom_a, atom_b, n_edges);
        int n_aq = (n_atoms + 3) / 4;
        lj_reduce_clear_v4<<<(n_aq + T - 1) / T, T>>>(out, n_atoms);
    } else {
        lj_zero_out<<<(n_atoms + T - 1) / T, T>>>(out, n_atoms);
        lj_edge_kernel_direct<<<(n_edges + T - 1) / T, T>>>(dist, atom_a, atom_b, out, n_edges);
    }
}

// round 9
// speedup vs baseline: 1.2650x; 1.2650x over previous
#include <cuda_runtime.h>
#include <cuda_bf16.h>
#include <cstdint>

// LJ constants (match reference); sigma=1, cutoff=5
#define EPSILON 1.0f
#define SHIFT_F (4.0f * (1.0f/244140625.0f - 1.0f/15625.0f))

// Replicated accumulation scratch, fully L2-resident (1.6 MB static).
// Contention ladder (edge-kernel time): NREP=1 ~85us, NREP=8/16/32 ~70us flat.
// NREP=4 halves zero+reduce overhead vs NREP=8; per-address concurrency
// still << 1 (400K counters vs ~300K resident threads).
#define NREP 4
#define MAX_ATOMS 100000
#define REP_STRIDE (MAX_ATOMS + 128)   // divisible by 4
__device__ __align__(16) float g_scratch[NREP * REP_STRIDE];

// Exact-size zero: one float4 per thread. (Separate zero kernel is
// load-bearing: R8's fused reduce-and-clear regressed 76.5 -> 101us.)
__global__ void __launch_bounds__(256)
lj_zero_scratch_v4(int n_vec4) {
    int i = blockIdx.x * blockDim.x + threadIdx.x;
    if (i < n_vec4)
        reinterpret_cast<float4*>(g_scratch)[i] = make_float4(0.f, 0.f, 0.f, 0.f);
}

__device__ __forceinline__ float lj_half_e(float x, float y, float z) {
    float r2   = fmaf(x, x, fmaf(y, y, z * z));
    float inv2 = 1.0f / r2;
    float sr6  = inv2 * inv2 * inv2;
    float e    = 4.0f * EPSILON * fmaf(sr6, sr6, -sr6) - SHIFT_F;
    return 0.5f * e;
}

// Scalar 1-edge/thread (proven best; kernel is REDG-lane-bound: 12.8M RED
// lanes x 1.29cyc / 148 SMs ~ 56us @NAT + load/issue overhead ~ 70us).
__global__ void __launch_bounds__(256)
lj_edge_kernel_rep(const float* __restrict__ dist,
                   const int* __restrict__ atom_a,
                   const int* __restrict__ atom_b,
                   int n_edges) {
    int i = blockIdx.x * blockDim.x + threadIdx.x;
    if (i >= n_edges) return;

    float x = dist[3 * i + 0];
    float y = dist[3 * i + 1];
    float z = dist[3 * i + 2];
    float h = lj_half_e(x, y, z);

    int ia = atom_a[i];
    int ib = atom_b[i];

    float* rep = g_scratch + (i & (NREP - 1)) * REP_STRIDE;
    atomicAdd(rep + ia, h);   // RED.ADD, fire-and-forget
    atomicAdd(rep + ib, h);
}

// Reduce NREP replicas -> out, 4 atoms/thread via float4 (NREP independent
// loads per thread = enough MLP at this size).
__global__ void __launch_bounds__(256)
lj_reduce_kernel_v4(float* __restrict__ out, int n_atoms) {
    int t = blockIdx.x * blockDim.x + threadIdx.x;
    int base = 4 * t;
    if (base >= n_atoms) return;

    float4 s = make_float4(0.f, 0.f, 0.f, 0.f);
    #pragma unroll
    for (int r = 0; r < NREP; r++) {
        const float4 v = *reinterpret_cast<const float4*>(
            g_scratch + r * REP_STRIDE + base);
        s.x += v.x; s.y += v.y; s.z += v.z; s.w += v.w;
    }
    if (base + 3 < n_atoms) {
        *reinterpret_cast<float4*>(out + base) = s;
    } else {
        float sv[4] = {s.x, s.y, s.z, s.w};
        for (int k = 0; k < 4 && base + k < n_atoms; k++) out[base + k] = sv[k];
    }
}

// Fallback (atom count exceeds static scratch): direct atomics.
__global__ void lj_zero_out(float* __restrict__ out, int n) {
    int i = blockIdx.x * blockDim.x + threadIdx.x;
    if (i < n) out[i] = 0.0f;
}
__global__ void lj_edge_kernel_direct(const float* __restrict__ dist,
                                      const int* __restrict__ atom_a,
                                      const int* __restrict__ atom_b,
                                      float* __restrict__ out,
                                      int n_edges) {
    int i = blockIdx.x * blockDim.x + threadIdx.x;
    if (i >= n_edges) return;
    float h = lj_half_e(dist[3*i], dist[3*i+1], dist[3*i+2]);
    atomicAdd(out + atom_a[i], h);
    atomicAdd(out + atom_b[i], h);
}

extern "C" void kernel_launch(void* const* d_in, const int* in_sizes, int n_in,
                              void* d_out, int out_size) {
    const float* dist   = (const float*)d_in[0];
    const int*   atom_a = (const int*)d_in[1];   // JAX x64-disabled: int32
    const int*   atom_b = (const int*)d_in[2];
    float* out = (float*)d_out;

    int n_edges = in_sizes[1];
    int n_atoms = out_size;
    const int T = 256;

    if (n_atoms <= MAX_ATOMS) {
        int n_vec4 = (NREP * REP_STRIDE) / 4;
        lj_zero_scratch_v4<<<(n_vec4 + T - 1) / T, T>>>(n_vec4);
        lj_edge_kernel_rep<<<(n_edges + T - 1) / T, T>>>(dist, atom_a, atom_b, n_edges);
        int n_aq = (n_atoms + 3) / 4;
        lj_reduce_kernel_v4<<<(n_aq + T - 1) / T, T>>>(out, n_atoms);
    } else {
        lj_zero_out<<<(n_atoms + T - 1) / T, T>>>(out, n_atoms);
        lj_edge_kernel_direct<<<(n_edges + T - 1) / T, T>>>(dist, atom_a, atom_b, out, n_edges);
    }
}

// round 10
// speedup vs baseline: 1.3244x; 1.0469x over previous
#include <cuda_runtime.h>
#include <cuda_bf16.h>
#include <cstdint>

// LJ constants (match reference); sigma=1, cutoff=5
#define EPSILON 1.0f
#define SHIFT_F (4.0f * (1.0f/244140625.0f - 1.0f/15625.0f))

// Replicated accumulation scratch, fully L2-resident (3.2 MB static).
// Contention ladder (edge-kernel time): NREP=1 ~85us, NREP=4 ~73us,
// NREP=8/16/32 ~70us flat. NREP=8 is the knee.
#define NREP 8
#define MAX_ATOMS 100000
#define REP_STRIDE (MAX_ATOMS + 128)   // divisible by 4
__device__ __align__(16) float g_scratch[NREP * REP_STRIDE];

__device__ __forceinline__ float lj_half_e(float x, float y, float z) {
    float r2   = fmaf(x, x, fmaf(y, y, z * z));
    float inv2 = 1.0f / r2;
    float sr6  = inv2 * inv2 * inv2;
    float e    = 4.0f * EPSILON * fmaf(sr6, sr6, -sr6) - SHIFT_F;
    return 0.5f * e;
}

// Scalar 1-edge/thread (proven best; REDG/LTS-atomic-bound at ~70us:
// 12.8M fp32 REDs / 184 LTS slices x ~2cyc/op — invariant across 4
// instruction-mix variants tested).
__global__ void __launch_bounds__(256)
lj_edge_kernel_rep(const float* __restrict__ dist,
                   const int* __restrict__ atom_a,
                   const int* __restrict__ atom_b,
                   int n_edges) {
    int i = blockIdx.x * blockDim.x + threadIdx.x;
    if (i >= n_edges) return;

    float x = dist[3 * i + 0];
    float y = dist[3 * i + 1];
    float z = dist[3 * i + 2];
    float h = lj_half_e(x, y, z);

    int ia = atom_a[i];
    int ib = atom_b[i];

    float* rep = g_scratch + (i & (NREP - 1)) * REP_STRIDE;
    atomicAdd(rep + ia, h);   // RED.ADD, fire-and-forget
    atomicAdd(rep + ib, h);
}

// Reduce NREP replicas -> out, 4 atoms/thread via float4.
__global__ void __launch_bounds__(256)
lj_reduce_kernel_v4(float* __restrict__ out, int n_atoms) {
    int t = blockIdx.x * blockDim.x + threadIdx.x;
    int base = 4 * t;
    if (base >= n_atoms) return;

    float4 s = make_float4(0.f, 0.f, 0.f, 0.f);
    #pragma unroll
    for (int r = 0; r < NREP; r++) {
        const float4 v = *reinterpret_cast<const float4*>(
            g_scratch + r * REP_STRIDE + base);
        s.x += v.x; s.y += v.y; s.z += v.z; s.w += v.w;
    }
    if (base + 3 < n_atoms) {
        *reinterpret_cast<float4*>(out + base) = s;
    } else {
        float sv[4] = {s.x, s.y, s.z, s.w};
        for (int k = 0; k < 4 && base + k < n_atoms; k++) out[base + k] = sv[k];
    }
}

// Fallback kernels (atom count exceeds static scratch): direct atomics.
__global__ void lj_zero_out(float* __restrict__ out, int n) {
    int i = blockIdx.x * blockDim.x + threadIdx.x;
    if (i < n) out[i] = 0.0f;
}
__global__ void lj_edge_kernel_direct(const float* __restrict__ dist,
                                      const int* __restrict__ atom_a,
                                      const int* __restrict__ atom_b,
                                      float* __restrict__ out,
                                      int n_edges) {
    int i = blockIdx.x * blockDim.x + threadIdx.x;
    if (i >= n_edges) return;
    float h = lj_half_e(dist[3*i], dist[3*i+1], dist[3*i+2]);
    atomicAdd(out + atom_a[i], h);
    atomicAdd(out + atom_b[i], h);
}

// Backup zero kernel in case symbol lookup ever fails (keeps path correct).
__global__ void __launch_bounds__(256)
lj_zero_scratch_v4(int n_vec4) {
    int i = blockIdx.x * blockDim.x + threadIdx.x;
    if (i < n_vec4)
        reinterpret_cast<float4*>(g_scratch)[i] = make_float4(0.f, 0.f, 0.f, 0.f);
}

extern "C" void kernel_launch(void* const* d_in, const int* in_sizes, int n_in,
                              void* d_out, int out_size) {
    const float* dist   = (const float*)d_in[0];
    const int*   atom_a = (const int*)d_in[1];   // JAX x64-disabled: int32
    const int*   atom_b = (const int*)d_in[2];
    float* out = (float*)d_out;

    int n_edges = in_sizes[1];
    int n_atoms = out_size;
    const int T = 256;

    if (n_atoms <= MAX_ATOMS) {
        // Zero scratch via a memset node: skips kernel-launch ramp
        // (the equivalent zero kernel measured 4.3-4.6us, latency-bound).
        void* scratch_ptr = nullptr;
        cudaError_t e = cudaGetSymbolAddress(&scratch_ptr, g_scratch);
        if (e == cudaSuccess && scratch_ptr != nullptr) {
            cudaMemsetAsync(scratch_ptr, 0, sizeof(float) * NREP * REP_STRIDE, 0);
        } else {
            int n_vec4 = (NREP * REP_STRIDE) / 4;
            lj_zero_scratch_v4<<<(n_vec4 + T - 1) / T, T>>>(n_vec4);
        }

        lj_edge_kernel_rep<<<(n_edges + T - 1) / T, T>>>(dist, atom_a, atom_b, n_edges);
        int n_aq = (n_atoms + 3) / 4;
        lj_reduce_kernel_v4<<<(n_aq + T - 1) / T, T>>>(out, n_atoms);
    } else {
        lj_zero_out<<<(n_atoms + T - 1) / T, T>>>(out, n_atoms);
        lj_edge_kernel_direct<<<(n_edges + T - 1) / T, T>>>(dist, atom_a, atom_b, out, n_edges);
    }
}

// round 11
// speedup vs baseline: 1.3255x; 1.0008x over previous
#include <cuda_runtime.h>
#include <cuda_bf16.h>
#include <cstdint>

// LJ constants (match reference); sigma=1, cutoff=5
#define EPSILON 1.0f
#define SHIFT_F (4.0f * (1.0f/244140625.0f - 1.0f/15625.0f))

// Replicated accumulation scratch, fully L2-resident (3.2 MB static).
// Contention ladder (edge-kernel time): NREP=1 ~85us, NREP=4 ~73us,
// NREP=8/16/32 ~70us flat. NREP=8 is the knee.
#define NREP 8
#define MAX_ATOMS 100000
#define REP_STRIDE (MAX_ATOMS + 128)   // divisible by 4
__device__ __align__(16) float g_scratch[NREP * REP_STRIDE];

__device__ __forceinline__ float lj_half_e(float x, float y, float z) {
    float r2   = fmaf(x, x, fmaf(y, y, z * z));
    float inv2 = 1.0f / r2;
    float sr6  = inv2 * inv2 * inv2;
    float e    = 4.0f * EPSILON * fmaf(sr6, sr6, -sr6) - SHIFT_F;
    return 0.5f * e;
}

// Scalar 1-edge/thread (proven best; REDG-lane-bound ~70us:
// 12.8M RED lanes x 1.29cyc / 148 SMs + load/issue overhead —
// invariant across 4 instruction-mix variants tested).
__global__ void __launch_bounds__(256)
lj_edge_kernel_rep(const float* __restrict__ dist,
                   const int* __restrict__ atom_a,
                   const int* __restrict__ atom_b,
                   int n_edges) {
    int i = blockIdx.x * blockDim.x + threadIdx.x;
    if (i >= n_edges) return;

    float x = dist[3 * i + 0];
    float y = dist[3 * i + 1];
    float z = dist[3 * i + 2];
    float h = lj_half_e(x, y, z);

    int ia = atom_a[i];
    int ib = atom_b[i];

    float* rep = g_scratch + (i & (NREP - 1)) * REP_STRIDE;
    atomicAdd(rep + ia, h);   // RED.ADD, fire-and-forget
    atomicAdd(rep + ib, h);
}

// Reduce NREP replicas -> out, 1 atom per thread (max parallelism:
// 391 blocks vs 98 for the float4 version, which sat at 12% occupancy
// and 5.2us, latency-bound). 8 independent coalesced LDG.32 per thread.
__global__ void __launch_bounds__(256)
lj_reduce_kernel_s(float* __restrict__ out, int n_atoms) {
    int i = blockIdx.x * blockDim.x + threadIdx.x;
    if (i >= n_atoms) return;

    float s = 0.0f;
    #pragma unroll
    for (int r = 0; r < NREP; r++)
        s += g_scratch[r * REP_STRIDE + i];
    out[i] = s;
}

// Fallback kernels (atom count exceeds static scratch): direct atomics.
__global__ void lj_zero_out(float* __restrict__ out, int n) {
    int i = blockIdx.x * blockDim.x + threadIdx.x;
    if (i < n) out[i] = 0.0f;
}
__global__ void lj_edge_kernel_direct(const float* __restrict__ dist,
                                      const int* __restrict__ atom_a,
                                      const int* __restrict__ atom_b,
                                      float* __restrict__ out,
                                      int n_edges) {
    int i = blockIdx.x * blockDim.x + threadIdx.x;
    if (i >= n_edges) return;
    float h = lj_half_e(dist[3*i], dist[3*i+1], dist[3*i+2]);
    atomicAdd(out + atom_a[i], h);
    atomicAdd(out + atom_b[i], h);
}

// Backup zero kernel in case symbol lookup ever fails.
__global__ void __launch_bounds__(256)
lj_zero_scratch_v4(int n_vec4) {
    int i = blockIdx.x * blockDim.x + threadIdx.x;
    if (i < n_vec4)
        reinterpret_cast<float4*>(g_scratch)[i] = make_float4(0.f, 0.f, 0.f, 0.f);
}

extern "C" void kernel_launch(void* const* d_in, const int* in_sizes, int n_in,
                              void* d_out, int out_size) {
    const float* dist   = (const float*)d_in[0];
    const int*   atom_a = (const int*)d_in[1];   // JAX x64-disabled: int32
    const int*   atom_b = (const int*)d_in[2];
    float* out = (float*)d_out;

    int n_edges = in_sizes[1];
    int n_atoms = out_size;
    const int T = 256;

    if (n_atoms <= MAX_ATOMS) {
        // Zero scratch via memset node (measured: beats the 4.3-4.6us
        // latency-bound zero kernel).
        void* scratch_ptr = nullptr;
        cudaError_t e = cudaGetSymbolAddress(&scratch_ptr, g_scratch);
        if (e == cudaSuccess && scratch_ptr != nullptr) {
            cudaMemsetAsync(scratch_ptr, 0, sizeof(float) * NREP * REP_STRIDE, 0);
        } else {
            int n_vec4 = (NREP * REP_STRIDE) / 4;
            lj_zero_scratch_v4<<<(n_vec4 + T - 1) / T, T>>>(n_vec4);
        }

        lj_edge_kernel_rep<<<(n_edges + T - 1) / T, T>>>(dist, atom_a, atom_b, n_edges);
        lj_reduce_kernel_s<<<(n_atoms + T - 1) / T, T>>>(out, n_atoms);
    } else {
        lj_zero_out<<<(n_atoms + T - 1) / T, T>>>(out, n_atoms);
        lj_edge_kernel_direct<<<(n_edges + T - 1) / T, T>>>(dist, atom_a, atom_b, out, n_edges);
    }
}